// round 14
// baseline (speedup 1.0000x reference)
#include <cuda_runtime.h>
#include <cstdint>

#define NN    50000
#define NE    800000
#define HD    64
#define MH    128
#define MHP   132    // padded stride (mod 32 == 4 -> conflict-free A-frags)
#define ET    64     // edge tile

// scratch
__device__ float g_agg[(size_t)NN * HD];
__device__ float g_Pcat[(size_t)NN * 256];   // [ h@W_src | h@W_dst + eb1 ]

__device__ __forceinline__ float f2tf(float f) {
    uint32_t u;
    asm("cvt.rna.tf32.f32 %0, %1;" : "=r"(u) : "f"(f));
    return __uint_as_float(u);
}

__device__ __forceinline__ void mma_tf32(float c[4], const uint32_t a[4],
                                         uint32_t b0, uint32_t b1) {
    asm volatile(
        "mma.sync.aligned.m16n8k8.row.col.f32.tf32.tf32.f32 "
        "{%0,%1,%2,%3},{%4,%5,%6,%7},{%8,%9},{%0,%1,%2,%3};"
        : "+f"(c[0]), "+f"(c[1]), "+f"(c[2]), "+f"(c[3])
        : "r"(a[0]), "r"(a[1]), "r"(a[2]), "r"(a[3]), "r"(b0), "r"(b1));
}

// ---------------------------------------------------------------------------
// prep (persistent): Pcat[n,0:128] = h@W_src ; Pcat[n,128:256] = h@W_dst + eb1
// Also zeroes g_agg rows. 148 blocks x 512 threads, weights loaded ONCE.
// ---------------------------------------------------------------------------
__global__ __launch_bounds__(512, 1)
void prep_kernel(const float* __restrict__ h, const float* __restrict__ eW1,
                 const float* __restrict__ eb1)
{
    extern __shared__ float sm[];
    float* sW = sm;             // 64 x 256, col-swizzled
    float* sA = sW + 64 * 256;  // 128 x 68

    const int tid  = threadIdx.x;
    const int lane = tid & 31;
    const int w    = tid >> 5;
    const int lq   = lane >> 2;
    const int lr   = lane & 3;

    for (int i = tid; i < 64 * 256; i += 512) {
        int k = i >> 8, c = i & 255;
        float v = (c < MH) ? eW1[k * MH + c] : eW1[(64 + k) * MH + (c - MH)];
        sW[k * 256 + (c ^ ((k & 3) << 3))] = f2tf(v);
    }

    const int mh = w >> 2, nc = w & 3;   // 4 (m32) x 4 (n64)
    const int numTiles = (NN + 127) / 128;   // 391

    for (int tile = blockIdx.x; tile < numTiles; tile += gridDim.x) {
        const int n0g = tile * 128;
        __syncthreads();

        for (int i = tid; i < 128 * 16; i += 512) {
            int r = i >> 4, c4 = i & 15;
            int node = n0g + r;
            if (node < NN)
                reinterpret_cast<float4*>(g_agg)[(size_t)node * 16 + c4] =
                    make_float4(0.f, 0.f, 0.f, 0.f);
        }
        for (int i = tid; i < 128 * 64; i += 512) {
            int r = i >> 6, c = i & 63;
            int node = min(n0g + r, NN - 1);
            sA[r * 68 + c] = f2tf(h[(size_t)node * HD + c]);
        }
        __syncthreads();

        float acc[2][8][4];
        #pragma unroll
        for (int i = 0; i < 2; i++)
            #pragma unroll
            for (int j = 0; j < 8; j++)
                #pragma unroll
                for (int q = 0; q < 4; q++) acc[i][j][q] = 0.f;

        for (int k = 0; k < 64; k += 8) {
            uint32_t a[2][4];
            #pragma unroll
            for (int i = 0; i < 2; i++) {
                int row = mh * 32 + 16 * i + lq;
                a[i][0] = __float_as_uint(sA[row * 68 + k + lr]);
                a[i][1] = __float_as_uint(sA[(row + 8) * 68 + k + lr]);
                a[i][2] = __float_as_uint(sA[row * 68 + k + 4 + lr]);
                a[i][3] = __float_as_uint(sA[(row + 8) * 68 + k + 4 + lr]);
            }
            #pragma unroll
            for (int j = 0; j < 8; j++) {
                int n0 = nc * 64 + 8 * j;
                int cs = (n0 + lq) ^ (lr << 3);
                uint32_t b0 = __float_as_uint(sW[(k + lr) * 256 + cs]);
                uint32_t b1 = __float_as_uint(sW[(k + 4 + lr) * 256 + cs]);
                mma_tf32(acc[0][j], a[0], b0, b1);
                mma_tf32(acc[1][j], a[1], b0, b1);
            }
        }

        #pragma unroll
        for (int i = 0; i < 2; i++) {
            int r0 = mh * 32 + 16 * i + lq;
            int g0 = n0g + r0, g1 = g0 + 8;
            #pragma unroll
            for (int j = 0; j < 8; j++) {
                int col = nc * 64 + 8 * j + 2 * lr;
                float bx = 0.f, by = 0.f;
                if (col >= MH) {
                    bx = eb1[col - MH];
                    by = eb1[col - MH + 1];
                }
                if (g0 < NN)
                    *(float2*)&g_Pcat[(size_t)g0 * 256 + col] =
                        make_float2(acc[i][j][0] + bx, acc[i][j][1] + by);
                if (g1 < NN)
                    *(float2*)&g_Pcat[(size_t)g1 * 256 + col] =
                        make_float2(acc[i][j][2] + bx, acc[i][j][3] + by);
            }
        }
    }
}

// ---------------------------------------------------------------------------
// Edge kernel v7: 3 CTAs/SM (occupancy replaces software prefetch).
// Direct loads at loop top, half-block barriers, SMSP-spread phase-2,
// lane-paired red.v4 scatter. Register diet: no prefetch regs, no hoisted
// B-fragments, per-tile bias reload (L1-hit).
// ---------------------------------------------------------------------------
__global__ __launch_bounds__(256, 3)
void edge_kernel(const int* __restrict__ ei,
                 const float* __restrict__ ea,
                 const float* __restrict__ eW1,
                 const float* __restrict__ eW2, const float* __restrict__ eb2)
{
    extern __shared__ float sm[];
    float* sWea = sm;                 // 8 x 128, col-swizzled
    float* sW2  = sWea + 8 * MH;      // 128 x 64, col-swizzled
    float* sH   = sW2 + MH * HD;      // 64 x 132

    const int tid  = threadIdx.x;
    const int lane = tid & 31;
    const int w    = tid >> 5;
    const int lq   = lane >> 2;
    const int lr   = lane & 3;
    const int mh   = w >> 2;
    const int nq   = w & 3;
    const int barid = 1 + mh;
    const bool p2act = (mh == 0) ? (nq < 2) : (nq >= 2);
    const int  nn    = nq & 1;

    for (int i = tid; i < 8 * MH; i += 256) {
        int k = i >> 7, c = i & 127;
        sWea[k * MH + (c ^ ((k & 3) << 3))] = f2tf(eW1[(2 * HD + k) * MH + c]);
    }
    for (int i = tid; i < MH * HD; i += 256) {
        int r = i >> 6, n = i & 63;
        sW2[r * HD + (n ^ ((r & 3) << 3))] = f2tf(eW2[i]);
    }
    __syncthreads();

    int rofs[4];
    #pragma unroll
    for (int q = 0; q < 4; q++)
        rofs[q] = mh * 32 + 16 * (q >> 1) + 8 * (q & 1) + lq;

    const int numTiles = NE / ET;   // 12500
    const int G = gridDim.x;

    for (int t = blockIdx.x; t < numTiles; t += G) {
        const int e0 = t * ET;

        // load this tile's indices + edge attrs directly into registers
        int cS[4], cD[4];
        uint32_t af[2][4];
        #pragma unroll
        for (int q = 0; q < 4; q++) {
            cS[q] = min(max(ei[e0 + rofs[q]], 0), NN - 1);
            cD[q] = min(max(ei[NE + e0 + rofs[q]], 0), NN - 1);
        }
        #pragma unroll
        for (int i = 0; i < 2; i++) {
            af[i][0] = __float_as_uint(f2tf(ea[(size_t)(e0 + rofs[2 * i])     * 8 + lr]));
            af[i][1] = __float_as_uint(f2tf(ea[(size_t)(e0 + rofs[2 * i + 1]) * 8 + lr]));
            af[i][2] = __float_as_uint(f2tf(ea[(size_t)(e0 + rofs[2 * i])     * 8 + 4 + lr]));
            af[i][3] = __float_as_uint(f2tf(ea[(size_t)(e0 + rofs[2 * i + 1]) * 8 + 4 + lr]));
        }

        // ---- phase 1: [64,8] @ [8,128] from registers (all 8 warps) ----
        float c1[2][4][4];
        #pragma unroll
        for (int i = 0; i < 2; i++)
            #pragma unroll
            for (int j = 0; j < 4; j++)
                #pragma unroll
                for (int q = 0; q < 4; q++) c1[i][j][q] = 0.f;

        #pragma unroll
        for (int j = 0; j < 4; j++) {
            int n0 = nq * 32 + 8 * j;
            int cs = (n0 + lq) ^ (lr << 3);
            uint32_t b0 = __float_as_uint(sWea[lr * MH + cs]);
            uint32_t b1 = __float_as_uint(sWea[(4 + lr) * MH + cs]);
            mma_tf32(c1[0][j], af[0], b0, b1);
            mma_tf32(c1[1][j], af[1], b0, b1);
        }

        // gathered Pcat (bias pre-folded), relu -> sH
        #pragma unroll
        for (int i = 0; i < 2; i++) {
            int r0 = rofs[2 * i];
            int r1 = rofs[2 * i + 1];
            const float* ps0 = g_Pcat + (size_t)cS[2 * i] * 256;
            const float* pd0 = g_Pcat + (size_t)cD[2 * i] * 256 + MH;
            const float* ps1 = g_Pcat + (size_t)cS[2 * i + 1] * 256;
            const float* pd1 = g_Pcat + (size_t)cD[2 * i + 1] * 256 + MH;
            #pragma unroll
            for (int j = 0; j < 4; j++) {
                int col = nq * 32 + 8 * j + 2 * lr;
                float2 s0 = *(const float2*)&ps0[col];
                float2 d0 = *(const float2*)&pd0[col];
                float2 s1 = *(const float2*)&ps1[col];
                float2 d1 = *(const float2*)&pd1[col];
                uint2 v0, v1;
                v0.x = __float_as_uint(f2tf(fmaxf(c1[i][j][0] + s0.x + d0.x, 0.f)));
                v0.y = __float_as_uint(f2tf(fmaxf(c1[i][j][1] + s0.y + d0.y, 0.f)));
                v1.x = __float_as_uint(f2tf(fmaxf(c1[i][j][2] + s1.x + d1.x, 0.f)));
                v1.y = __float_as_uint(f2tf(fmaxf(c1[i][j][3] + s1.y + d1.y, 0.f)));
                *(uint2*)&sH[r0 * MHP + col] = v0;
                *(uint2*)&sH[r1 * MHP + col] = v1;
            }
        }

        // half-block barrier: this m-half's sH writes visible to its warps
        asm volatile("bar.sync %0, 128;" :: "r"(barid) : "memory");

        // ---- phase 2: [32,128] @ [128,32] per active warp (SMSP-spread) ----
        float c2[2][4][4];
        if (p2act) {
            #pragma unroll
            for (int i = 0; i < 2; i++)
                #pragma unroll
                for (int j = 0; j < 4; j++)
                    #pragma unroll
                    for (int q = 0; q < 4; q++) c2[i][j][q] = 0.f;

            for (int k = 0; k < MH; k += 8) {
                uint32_t a[2][4];
                #pragma unroll
                for (int i = 0; i < 2; i++) {
                    int row = rofs[2 * i];
                    a[i][0] = __float_as_uint(sH[row * MHP + k + lr]);
                    a[i][1] = __float_as_uint(sH[(row + 8) * MHP + k + lr]);
                    a[i][2] = __float_as_uint(sH[row * MHP + k + 4 + lr]);
                    a[i][3] = __float_as_uint(sH[(row + 8) * MHP + k + 4 + lr]);
                }
                #pragma unroll
                for (int j = 0; j < 4; j++) {
                    int n0 = nn * 32 + 8 * j;
                    int cs = (n0 + lq) ^ (lr << 3);
                    uint32_t b0 = __float_as_uint(sW2[(k + lr) * HD + cs]);
                    uint32_t b1 = __float_as_uint(sW2[(k + 4 + lr) * HD + cs]);
                    mma_tf32(c2[0][j], a[0], b0, b1);
                    mma_tf32(c2[1][j], a[1], b0, b1);
                }
            }
        }

        // half-block barrier: sH reads done before next tile overwrites
        asm volatile("bar.sync %0, 128;" :: "r"(barid) : "memory");

        // scatter-add (active warps only; bias loaded per tile, L1-hit)
        if (p2act) {
            #pragma unroll
            for (int i = 0; i < 2; i++) {
                int d0 = cD[2 * i], d1 = cD[2 * i + 1];
                #pragma unroll
                for (int j = 0; j < 4; j++) {
                    float2 bj = *(const float2*)&eb2[nn * 32 + 8 * j + 2 * lr];
                    float u0 = c2[i][j][0] + bj.x;
                    float u1 = c2[i][j][1] + bj.y;
                    float u2 = c2[i][j][2] + bj.x;
                    float u3 = c2[i][j][3] + bj.y;
                    float w0 = __shfl_xor_sync(0xffffffffu, u0, 1);
                    float w1 = __shfl_xor_sync(0xffffffffu, u1, 1);
                    float w2 = __shfl_xor_sync(0xffffffffu, u2, 1);
                    float w3 = __shfl_xor_sync(0xffffffffu, u3, 1);
                    if (!(lr & 1)) {
                        int col = nn * 32 + 8 * j + (lr & 2) * 2;
                        float* p0 = g_agg + (size_t)d0 * HD + col;
                        float* p1 = g_agg + (size_t)d1 * HD + col;
                        asm volatile("red.global.add.v4.f32 [%0], {%1, %2, %3, %4};"
                                     :: "l"(p0), "f"(u0), "f"(u1), "f"(w0), "f"(w1)
                                     : "memory");
                        asm volatile("red.global.add.v4.f32 [%0], {%1, %2, %3, %4};"
                                     :: "l"(p1), "f"(u2), "f"(u3), "f"(w2), "f"(w3)
                                     : "memory");
                    }
                }
            }
        }
    }
}

// ---------------------------------------------------------------------------
// Node kernel v2 (R13): half-block decoupled, shuffle-based LayerNorm stats.
// ---------------------------------------------------------------------------
#define TILE 64
__global__ __launch_bounds__(256, 1)
void node_kernel(const float* __restrict__ h,
                 const float* __restrict__ nW1, const float* __restrict__ nb1,
                 const float* __restrict__ nW2, const float* __restrict__ nb2,
                 const float* __restrict__ lg,  const float* __restrict__ lb,
                 float* __restrict__ out)
{
    extern __shared__ float sm[];
    float* sW1 = sm;                    // 128x128 swizzled
    float* sW2 = sW1 + MH * MH;         // 128x64 swizzled
    float* sU  = sW2 + MH * HD;         // 64 x 132
    float* sH  = sU  + TILE * MHP;      // 64 x 132
    float* sO  = sH  + TILE * MHP;      // 64 x 65
    float* sP  = sO  + TILE * 65;       // 64 x 4
    float* sB1 = sP  + TILE * 4;        // 128
    float* sB2 = sB1 + MH;              // 64
    float* sG  = sB2 + HD;              // 64
    float* sB  = sG  + HD;              // 64

    const int tid  = threadIdx.x;
    const int lane = tid & 31;
    const int w    = tid >> 5;
    const int lq   = lane >> 2;
    const int lr   = lane & 3;
    const int mh   = w >> 2;
    const int nq   = w & 3;
    const int mi   = nq >> 1;
    const int ni   = nq & 1;
    const int t128 = tid & 127;
    const int barid = 1 + mh;

    for (int i = tid; i < MH * MH; i += 256) {
        int r = i >> 7, n = i & 127;
        sW1[r * MH + (n ^ ((r & 3) << 3))] = f2tf(nW1[i]);
    }
    for (int i = tid; i < MH * HD; i += 256) {
        int r = i >> 6, n = i & 63;
        sW2[r * HD + (n ^ ((r & 3) << 3))] = f2tf(nW2[i]);
    }
    for (int i = tid; i < MH; i += 256) sB1[i] = nb1[i];
    if (tid < HD) { sB2[tid] = nb2[tid]; sG[tid] = lg[tid]; sB[tid] = lb[tid]; }
    __syncthreads();

    float2 b1p[4], b2p[4];
    #pragma unroll
    for (int j = 0; j < 4; j++) {
        b1p[j] = *(const float2*)&sB1[nq * 32 + 8 * j + 2 * lr];
        b2p[j] = *(const float2*)&sB2[ni * 32 + 8 * j + 2 * lr];
    }

    const int numTiles = (NN + TILE - 1) / TILE;

    float pf[32];
    int t = blockIdx.x;
    if (t < numTiles) {
        const int n0g = t * TILE;
        #pragma unroll
        for (int v = 0; v < 32; v++) {
            int node = min(n0g + mh * 32 + v, NN - 1);
            pf[v] = (t128 < HD) ? h[(size_t)node * HD + t128]
                                : g_agg[(size_t)node * HD + (t128 - HD)];
        }
    }

    for (; t < numTiles; t += gridDim.x) {
        const int n0g = t * TILE;

        #pragma unroll
        for (int v = 0; v < 32; v++)
            sU[(mh * 32 + v) * MHP + t128] = f2tf(pf[v]);

        asm volatile("bar.sync %0, 128;" :: "r"(barid) : "memory");  // (A)

        int tn = t + gridDim.x;
        if (tn < numTiles) {
            const int nn0 = tn * TILE;
            #pragma unroll
            for (int v = 0; v < 32; v++) {
                int node = min(nn0 + mh * 32 + v, NN - 1);
                pf[v] = (t128 < HD) ? h[(size_t)node * HD + t128]
                                    : g_agg[(size_t)node * HD + (t128 - HD)];
            }
        }

        float c1[2][4][4];
        #pragma unroll
        for (int i = 0; i < 2; i++)
            #pragma unroll
            for (int j = 0; j < 4; j++)
                #pragma unroll
                for (int q = 0; q < 4; q++) c1[i][j][q] = 0.f;

        for (int k = 0; k < MH; k += 8) {
            uint32_t a[2][4];
            #pragma unroll
            for (int i = 0; i < 2; i++) {
                int row = mh * 32 + 16 * i + lq;
                a[i][0] = __float_as_uint(sU[row * MHP + k + lr]);
                a[i][1] = __float_as_uint(sU[(row + 8) * MHP + k + lr]);
                a[i][2] = __float_as_uint(sU[row * MHP + k + 4 + lr]);
                a[i][3] = __float_as_uint(sU[(row + 8) * MHP + k + 4 + lr]);
            }
            #pragma unroll
            for (int j = 0; j < 4; j++) {
                int n0 = nq * 32 + 8 * j;
                int cs = (n0 + lq) ^ (lr << 3);
                uint32_t b0 = __float_as_uint(sW1[(k + lr) * MH + cs]);
                uint32_t b1 = __float_as_uint(sW1[(k + 4 + lr) * MH + cs]);
                mma_tf32(c1[0][j], a[0], b0, b1);
                mma_tf32(c1[1][j], a[1], b0, b1);
            }
        }

        #pragma unroll
        for (int i = 0; i < 2; i++) {
            #pragma unroll
            for (int j = 0; j < 4; j++) {
                int row = mh * 32 + 16 * i + lq;
                int col = nq * 32 + 8 * j + 2 * lr;
                uint2 v0, v1;
                v0.x = __float_as_uint(f2tf(fmaxf(c1[i][j][0] + b1p[j].x, 0.f)));
                v0.y = __float_as_uint(f2tf(fmaxf(c1[i][j][1] + b1p[j].y, 0.f)));
                v1.x = __float_as_uint(f2tf(fmaxf(c1[i][j][2] + b1p[j].x, 0.f)));
                v1.y = __float_as_uint(f2tf(fmaxf(c1[i][j][3] + b1p[j].y, 0.f)));
                *(uint2*)&sH[row * MHP + col]       = v0;
                *(uint2*)&sH[(row + 8) * MHP + col] = v1;
            }
        }

        asm volatile("bar.sync %0, 128;" :: "r"(barid) : "memory");  // (B)

        float c2[4][4];
        #pragma unroll
        for (int j = 0; j < 4; j++)
            #pragma unroll
            for (int q = 0; q < 4; q++) c2[j][q] = 0.f;

        const int m0 = mh * 32 + mi * 16;
        for (int k = 0; k < MH; k += 8) {
            uint32_t a[4];
            int row = m0 + lq;
            a[0] = __float_as_uint(sH[row * MHP + k + lr]);
            a[1] = __float_as_uint(sH[(row + 8) * MHP + k + lr]);
            a[2] = __float_as_uint(sH[row * MHP + k + 4 + lr]);
            a[3] = __float_as_uint(sH[(row + 8) * MHP + k + 4 + lr]);
            #pragma unroll
            for (int j = 0; j < 4; j++) {
                int n0 = ni * 32 + 8 * j;
                int cs = (n0 + lq) ^ (lr << 3);
                uint32_t b0 = __float_as_uint(sW2[(k + lr) * HD + cs]);
                uint32_t b1 = __float_as_uint(sW2[(k + 4 + lr) * HD + cs]);
                mma_tf32(c2[j], a, b0, b1);
            }
        }

        {
            int r0 = m0 + lq;
            int r1 = r0 + 8;
            int g0 = min(n0g + r0, NN - 1);
            int g1 = min(n0g + r1, NN - 1);
            float s0 = 0.f, q0 = 0.f, s1 = 0.f, q1 = 0.f;
            #pragma unroll
            for (int j = 0; j < 4; j++) {
                int col = ni * 32 + 8 * j + 2 * lr;
                float2 h0 = *(const float2*)&h[(size_t)g0 * HD + col];
                float2 h1 = *(const float2*)&h[(size_t)g1 * HD + col];
                float x0 = c2[j][0] + b2p[j].x + h0.x;
                float x1 = c2[j][1] + b2p[j].y + h0.y;
                float x2 = c2[j][2] + b2p[j].x + h1.x;
                float x3 = c2[j][3] + b2p[j].y + h1.y;
                sO[r0 * 65 + col]     = x0;
                sO[r0 * 65 + col + 1] = x1;
                sO[r1 * 65 + col]     = x2;
                sO[r1 * 65 + col + 1] = x3;
                s0 += x0 + x1;  q0 = fmaf(x0, x0, fmaf(x1, x1, q0));
                s1 += x2 + x3;  q1 = fmaf(x2, x2, fmaf(x3, x3, q1));
            }
            s0 += __shfl_xor_sync(0xffffffffu, s0, 1);
            s0 += __shfl_xor_sync(0xffffffffu, s0, 2);
            q0 += __shfl_xor_sync(0xffffffffu, q0, 1);
            q0 += __shfl_xor_sync(0xffffffffu, q0, 2);
            s1 += __shfl_xor_sync(0xffffffffu, s1, 1);
            s1 += __shfl_xor_sync(0xffffffffu, s1, 2);
            q1 += __shfl_xor_sync(0xffffffffu, q1, 1);
            q1 += __shfl_xor_sync(0xffffffffu, q1, 2);
            if (lr == 0) {
                sP[r0 * 4 + ni * 2 + 0] = s0;
                sP[r0 * 4 + ni * 2 + 1] = q0;
                sP[r1 * 4 + ni * 2 + 0] = s1;
                sP[r1 * 4 + ni * 2 + 1] = q1;
            }
        }

        asm volatile("bar.sync %0, 128;" :: "r"(barid) : "memory");  // (C)

        {
            int r_l  = mh * 32 + (t128 >> 2);
            int c0   = (t128 & 3) * 16;
            int node = n0g + r_l;
            if (node < NN) {
                float s  = sP[r_l * 4 + 0] + sP[r_l * 4 + 2];
                float q  = sP[r_l * 4 + 1] + sP[r_l * 4 + 3];
                float mu = s * (1.f / HD);
                float vr = fmaxf(q * (1.f / HD) - mu * mu, 0.f);
                float rs = rsqrtf(vr + 1e-5f);
                #pragma unroll
                for (int c = 0; c < 16; c += 2) {
                    float a0 = (sO[r_l * 65 + c0 + c]     - mu) * rs * sG[c0 + c]     + sB[c0 + c];
                    float a1 = (sO[r_l * 65 + c0 + c + 1] - mu) * rs * sG[c0 + c + 1] + sB[c0 + c + 1];
                    *(float2*)&out[(size_t)node * HD + c0 + c] = make_float2(a0, a1);
                }
            }
        }

        asm volatile("bar.sync %0, 128;" :: "r"(barid) : "memory");  // (D)
    }
}

// ---------------------------------------------------------------------------
extern "C" void kernel_launch(void* const* d_in, const int* in_sizes, int n_in,
                              void* d_out, int out_size)
{
    const float* h   = (const float*)d_in[0];
    const int*   ei  = (const int*)d_in[1];     // int32 (JAX default downcast)
    const float* ea  = (const float*)d_in[2];
    const float* eW1 = (const float*)d_in[3];
    const float* eb1 = (const float*)d_in[4];
    const float* eW2 = (const float*)d_in[5];
    const float* eb2 = (const float*)d_in[6];
    const float* nW1 = (const float*)d_in[7];
    const float* nb1 = (const float*)d_in[8];
    const float* nW2 = (const float*)d_in[9];
    const float* nb2 = (const float*)d_in[10];
    const float* lg  = (const float*)d_in[11];
    const float* lb  = (const float*)d_in[12];
    float*       out = (float*)d_out;

    const int smem_prep = (64 * 256 + 128 * 68) * 4;
    const int smem_edge = (8 * MH + MH * HD + ET * MHP) * 4;
    const int smem_node = (MH * MH + MH * HD + 2 * TILE * MHP + TILE * 65
                           + TILE * 4 + MH + 3 * HD) * 4;

    cudaFuncSetAttribute(prep_kernel, cudaFuncAttributeMaxDynamicSharedMemorySize, smem_prep);
    cudaFuncSetAttribute(edge_kernel, cudaFuncAttributeMaxDynamicSharedMemorySize, smem_edge);
    cudaFuncSetAttribute(node_kernel, cudaFuncAttributeMaxDynamicSharedMemorySize, smem_node);

    prep_kernel<<<148, 512, smem_prep>>>(h, eW1, eb1);
    edge_kernel<<<444, 256, smem_edge>>>(ei, ea, eW1, eW2, eb2);
    node_kernel<<<148, 256, smem_node>>>(h, nW1, nb1, nW2, nb2, lg, lb, out);
}

// round 15
// speedup vs baseline: 1.0060x; 1.0060x over previous
#include <cuda_runtime.h>
#include <cstdint>

#define NN    50000
#define NE    800000
#define HD    64
#define MH    128
#define MHP   132    // padded stride (mod 32 == 4 -> conflict-free A-frags)
#define ET    64     // edge tile

// scratch
__device__ float g_agg[(size_t)NN * HD];
__device__ float g_Pcat[(size_t)NN * 256];   // [ h@W_src | h@W_dst + eb1 ]

__device__ __forceinline__ float f2tf(float f) {
    uint32_t u;
    asm("cvt.rna.tf32.f32 %0, %1;" : "=r"(u) : "f"(f));
    return __uint_as_float(u);
}

__device__ __forceinline__ void mma_tf32(float c[4], const uint32_t a[4],
                                         uint32_t b0, uint32_t b1) {
    asm volatile(
        "mma.sync.aligned.m16n8k8.row.col.f32.tf32.tf32.f32 "
        "{%0,%1,%2,%3},{%4,%5,%6,%7},{%8,%9},{%0,%1,%2,%3};"
        : "+f"(c[0]), "+f"(c[1]), "+f"(c[2]), "+f"(c[3])
        : "r"(a[0]), "r"(a[1]), "r"(a[2]), "r"(a[3]), "r"(b0), "r"(b1));
}

// ---------------------------------------------------------------------------
// prep (persistent): Pcat[n,0:128] = h@W_src ; Pcat[n,128:256] = h@W_dst + eb1
// Also zeroes g_agg rows. 148 blocks x 512 threads, weights loaded ONCE.
// ---------------------------------------------------------------------------
__global__ __launch_bounds__(512, 1)
void prep_kernel(const float* __restrict__ h, const float* __restrict__ eW1,
                 const float* __restrict__ eb1)
{
    extern __shared__ float sm[];
    float* sW = sm;             // 64 x 256, col-swizzled
    float* sA = sW + 64 * 256;  // 128 x 68

    const int tid  = threadIdx.x;
    const int lane = tid & 31;
    const int w    = tid >> 5;
    const int lq   = lane >> 2;
    const int lr   = lane & 3;

    for (int i = tid; i < 64 * 256; i += 512) {
        int k = i >> 8, c = i & 255;
        float v = (c < MH) ? eW1[k * MH + c] : eW1[(64 + k) * MH + (c - MH)];
        sW[k * 256 + (c ^ ((k & 3) << 3))] = f2tf(v);
    }

    const int mh = w >> 2, nc = w & 3;   // 4 (m32) x 4 (n64)
    const int numTiles = (NN + 127) / 128;   // 391

    for (int tile = blockIdx.x; tile < numTiles; tile += gridDim.x) {
        const int n0g = tile * 128;
        __syncthreads();

        for (int i = tid; i < 128 * 16; i += 512) {
            int r = i >> 4, c4 = i & 15;
            int node = n0g + r;
            if (node < NN)
                reinterpret_cast<float4*>(g_agg)[(size_t)node * 16 + c4] =
                    make_float4(0.f, 0.f, 0.f, 0.f);
        }
        for (int i = tid; i < 128 * 64; i += 512) {
            int r = i >> 6, c = i & 63;
            int node = min(n0g + r, NN - 1);
            sA[r * 68 + c] = f2tf(h[(size_t)node * HD + c]);
        }
        __syncthreads();

        float acc[2][8][4];
        #pragma unroll
        for (int i = 0; i < 2; i++)
            #pragma unroll
            for (int j = 0; j < 8; j++)
                #pragma unroll
                for (int q = 0; q < 4; q++) acc[i][j][q] = 0.f;

        for (int k = 0; k < 64; k += 8) {
            uint32_t a[2][4];
            #pragma unroll
            for (int i = 0; i < 2; i++) {
                int row = mh * 32 + 16 * i + lq;
                a[i][0] = __float_as_uint(sA[row * 68 + k + lr]);
                a[i][1] = __float_as_uint(sA[(row + 8) * 68 + k + lr]);
                a[i][2] = __float_as_uint(sA[row * 68 + k + 4 + lr]);
                a[i][3] = __float_as_uint(sA[(row + 8) * 68 + k + 4 + lr]);
            }
            #pragma unroll
            for (int j = 0; j < 8; j++) {
                int n0 = nc * 64 + 8 * j;
                int cs = (n0 + lq) ^ (lr << 3);
                uint32_t b0 = __float_as_uint(sW[(k + lr) * 256 + cs]);
                uint32_t b1 = __float_as_uint(sW[(k + 4 + lr) * 256 + cs]);
                mma_tf32(acc[0][j], a[0], b0, b1);
                mma_tf32(acc[1][j], a[1], b0, b1);
            }
        }

        #pragma unroll
        for (int i = 0; i < 2; i++) {
            int r0 = mh * 32 + 16 * i + lq;
            int g0 = n0g + r0, g1 = g0 + 8;
            #pragma unroll
            for (int j = 0; j < 8; j++) {
                int col = nc * 64 + 8 * j + 2 * lr;
                float bx = 0.f, by = 0.f;
                if (col >= MH) {
                    bx = eb1[col - MH];
                    by = eb1[col - MH + 1];
                }
                if (g0 < NN)
                    *(float2*)&g_Pcat[(size_t)g0 * 256 + col] =
                        make_float2(acc[i][j][0] + bx, acc[i][j][1] + by);
                if (g1 < NN)
                    *(float2*)&g_Pcat[(size_t)g1 * 256 + col] =
                        make_float2(acc[i][j][2] + bx, acc[i][j][3] + by);
            }
        }
    }
}

// ---------------------------------------------------------------------------
// Edge kernel (R13 config: 2 CTAs/SM, reg prefetch, hoisted phase-1 B-frags,
// half-block barriers, SMSP-spread phase-2, red.v4 scatter).
// NEW: Pcat epilogue loads batched per i-block + __ldg read-only path.
// ---------------------------------------------------------------------------
__global__ __launch_bounds__(256, 2)
void edge_kernel(const int* __restrict__ ei,
                 const float* __restrict__ ea,
                 const float* __restrict__ eW1,
                 const float* __restrict__ eW2, const float* __restrict__ eb2)
{
    extern __shared__ float sm[];
    float* sWea = sm;                 // 8 x 128, col-swizzled
    float* sW2  = sWea + 8 * MH;      // 128 x 64, col-swizzled
    float* sH   = sW2 + MH * HD;      // 64 x 132

    const int tid  = threadIdx.x;
    const int lane = tid & 31;
    const int w    = tid >> 5;
    const int lq   = lane >> 2;
    const int lr   = lane & 3;
    const int mh   = w >> 2;
    const int nq   = w & 3;
    const int barid = 1 + mh;
    const bool p2act = (mh == 0) ? (nq < 2) : (nq >= 2);
    const int  nn    = nq & 1;

    for (int i = tid; i < 8 * MH; i += 256) {
        int k = i >> 7, c = i & 127;
        sWea[k * MH + (c ^ ((k & 3) << 3))] = f2tf(eW1[(2 * HD + k) * MH + c]);
    }
    for (int i = tid; i < MH * HD; i += 256) {
        int r = i >> 6, n = i & 63;
        sW2[r * HD + (n ^ ((r & 3) << 3))] = f2tf(eW2[i]);
    }
    __syncthreads();

    uint32_t wb0[4], wb1[4];
    #pragma unroll
    for (int j = 0; j < 4; j++) {
        int n0 = nq * 32 + 8 * j;
        int cs = (n0 + lq) ^ (lr << 3);
        wb0[j] = __float_as_uint(sWea[lr * MH + cs]);
        wb1[j] = __float_as_uint(sWea[(4 + lr) * MH + cs]);
    }

    float2 b2p[4];
    #pragma unroll
    for (int j = 0; j < 4; j++)
        b2p[j] = *(const float2*)&eb2[nn * 32 + 8 * j + 2 * lr];

    int rofs[4];
    #pragma unroll
    for (int q = 0; q < 4; q++)
        rofs[q] = mh * 32 + 16 * (q >> 1) + 8 * (q & 1) + lq;

    const int numTiles = NE / ET;
    const int G = gridDim.x;

    int nS[4], nD[4];
    float nA[8];
    int t = blockIdx.x;
    if (t < numTiles) {
        const int e0 = t * ET;
        #pragma unroll
        for (int q = 0; q < 4; q++) {
            nS[q] = ei[e0 + rofs[q]];
            nD[q] = ei[NE + e0 + rofs[q]];
        }
        #pragma unroll
        for (int i = 0; i < 2; i++) {
            nA[4 * i + 0] = ea[(size_t)(e0 + rofs[2 * i])     * 8 + lr];
            nA[4 * i + 1] = ea[(size_t)(e0 + rofs[2 * i + 1]) * 8 + lr];
            nA[4 * i + 2] = ea[(size_t)(e0 + rofs[2 * i])     * 8 + 4 + lr];
            nA[4 * i + 3] = ea[(size_t)(e0 + rofs[2 * i + 1]) * 8 + 4 + lr];
        }
    }

    for (; t < numTiles; t += G) {
        int cS[4], cD[4];
        uint32_t af[2][4];
        #pragma unroll
        for (int q = 0; q < 4; q++) {
            cS[q] = min(max(nS[q], 0), NN - 1);
            cD[q] = min(max(nD[q], 0), NN - 1);
        }
        #pragma unroll
        for (int i = 0; i < 2; i++)
            #pragma unroll
            for (int q = 0; q < 4; q++)
                af[i][q] = __float_as_uint(f2tf(nA[4 * i + q]));

        int tn = t + G;
        if (tn < numTiles) {
            const int en = tn * ET;
            #pragma unroll
            for (int q = 0; q < 4; q++) {
                nS[q] = ei[en + rofs[q]];
                nD[q] = ei[NE + en + rofs[q]];
            }
            #pragma unroll
            for (int i = 0; i < 2; i++) {
                nA[4 * i + 0] = ea[(size_t)(en + rofs[2 * i])     * 8 + lr];
                nA[4 * i + 1] = ea[(size_t)(en + rofs[2 * i + 1]) * 8 + lr];
                nA[4 * i + 2] = ea[(size_t)(en + rofs[2 * i])     * 8 + 4 + lr];
                nA[4 * i + 3] = ea[(size_t)(en + rofs[2 * i + 1]) * 8 + 4 + lr];
            }
        }

        float c1[2][4][4];
        #pragma unroll
        for (int i = 0; i < 2; i++)
            #pragma unroll
            for (int j = 0; j < 4; j++)
                #pragma unroll
                for (int q = 0; q < 4; q++) c1[i][j][q] = 0.f;

        #pragma unroll
        for (int j = 0; j < 4; j++) {
            mma_tf32(c1[0][j], af[0], wb0[j], wb1[j]);
            mma_tf32(c1[1][j], af[1], wb0[j], wb1[j]);
        }

        // gathered Pcat (bias pre-folded), relu -> sH
        // loads batched per i-block through the read-only path (MLP=16)
        #pragma unroll
        for (int i = 0; i < 2; i++) {
            int r0 = rofs[2 * i];
            int r1 = rofs[2 * i + 1];
            const float2* ps0 = (const float2*)(g_Pcat + (size_t)cS[2 * i] * 256);
            const float2* pd0 = (const float2*)(g_Pcat + (size_t)cD[2 * i] * 256 + MH);
            const float2* ps1 = (const float2*)(g_Pcat + (size_t)cS[2 * i + 1] * 256);
            const float2* pd1 = (const float2*)(g_Pcat + (size_t)cD[2 * i + 1] * 256 + MH);
            float2 sv0[4], dv0[4], sv1[4], dv1[4];
            #pragma unroll
            for (int j = 0; j < 4; j++) {
                int c2i = (nq * 32 + 8 * j + 2 * lr) >> 1;
                sv0[j] = __ldg(&ps0[c2i]);
                dv0[j] = __ldg(&pd0[c2i]);
                sv1[j] = __ldg(&ps1[c2i]);
                dv1[j] = __ldg(&pd1[c2i]);
            }
            #pragma unroll
            for (int j = 0; j < 4; j++) {
                int col = nq * 32 + 8 * j + 2 * lr;
                uint2 v0, v1;
                v0.x = __float_as_uint(f2tf(fmaxf(c1[i][j][0] + sv0[j].x + dv0[j].x, 0.f)));
                v0.y = __float_as_uint(f2tf(fmaxf(c1[i][j][1] + sv0[j].y + dv0[j].y, 0.f)));
                v1.x = __float_as_uint(f2tf(fmaxf(c1[i][j][2] + sv1[j].x + dv1[j].x, 0.f)));
                v1.y = __float_as_uint(f2tf(fmaxf(c1[i][j][3] + sv1[j].y + dv1[j].y, 0.f)));
                *(uint2*)&sH[r0 * MHP + col] = v0;
                *(uint2*)&sH[r1 * MHP + col] = v1;
            }
        }

        asm volatile("bar.sync %0, 128;" :: "r"(barid) : "memory");

        float c2[2][4][4];
        if (p2act) {
            #pragma unroll
            for (int i = 0; i < 2; i++)
                #pragma unroll
                for (int j = 0; j < 4; j++)
                    #pragma unroll
                    for (int q = 0; q < 4; q++) c2[i][j][q] = 0.f;

            for (int k = 0; k < MH; k += 8) {
                uint32_t a[2][4];
                #pragma unroll
                for (int i = 0; i < 2; i++) {
                    int row = rofs[2 * i];
                    a[i][0] = __float_as_uint(sH[row * MHP + k + lr]);
                    a[i][1] = __float_as_uint(sH[(row + 8) * MHP + k + lr]);
                    a[i][2] = __float_as_uint(sH[row * MHP + k + 4 + lr]);
                    a[i][3] = __float_as_uint(sH[(row + 8) * MHP + k + 4 + lr]);
                }
                #pragma unroll
                for (int j = 0; j < 4; j++) {
                    int n0 = nn * 32 + 8 * j;
                    int cs = (n0 + lq) ^ (lr << 3);
                    uint32_t b0 = __float_as_uint(sW2[(k + lr) * HD + cs]);
                    uint32_t b1 = __float_as_uint(sW2[(k + 4 + lr) * HD + cs]);
                    mma_tf32(c2[0][j], a[0], b0, b1);
                    mma_tf32(c2[1][j], a[1], b0, b1);
                }
            }
        }

        asm volatile("bar.sync %0, 128;" :: "r"(barid) : "memory");

        if (p2act) {
            #pragma unroll
            for (int i = 0; i < 2; i++) {
                int d0 = cD[2 * i], d1 = cD[2 * i + 1];
                #pragma unroll
                for (int j = 0; j < 4; j++) {
                    float u0 = c2[i][j][0] + b2p[j].x;
                    float u1 = c2[i][j][1] + b2p[j].y;
                    float u2 = c2[i][j][2] + b2p[j].x;
                    float u3 = c2[i][j][3] + b2p[j].y;
                    float w0 = __shfl_xor_sync(0xffffffffu, u0, 1);
                    float w1 = __shfl_xor_sync(0xffffffffu, u1, 1);
                    float w2 = __shfl_xor_sync(0xffffffffu, u2, 1);
                    float w3 = __shfl_xor_sync(0xffffffffu, u3, 1);
                    if (!(lr & 1)) {
                        int col = nn * 32 + 8 * j + (lr & 2) * 2;
                        float* p0 = g_agg + (size_t)d0 * HD + col;
                        float* p1 = g_agg + (size_t)d1 * HD + col;
                        asm volatile("red.global.add.v4.f32 [%0], {%1, %2, %3, %4};"
                                     :: "l"(p0), "f"(u0), "f"(u1), "f"(w0), "f"(w1)
                                     : "memory");
                        asm volatile("red.global.add.v4.f32 [%0], {%1, %2, %3, %4};"
                                     :: "l"(p1), "f"(u2), "f"(u3), "f"(w2), "f"(w3)
                                     : "memory");
                    }
                }
            }
        }
    }
}

// ---------------------------------------------------------------------------
// Node kernel v2 (R13): half-block decoupled, shuffle-based LayerNorm stats.
// ---------------------------------------------------------------------------
#define TILE 64
__global__ __launch_bounds__(256, 1)
void node_kernel(const float* __restrict__ h,
                 const float* __restrict__ nW1, const float* __restrict__ nb1,
                 const float* __restrict__ nW2, const float* __restrict__ nb2,
                 const float* __restrict__ lg,  const float* __restrict__ lb,
                 float* __restrict__ out)
{
    extern __shared__ float sm[];
    float* sW1 = sm;
    float* sW2 = sW1 + MH * MH;
    float* sU  = sW2 + MH * HD;
    float* sH  = sU  + TILE * MHP;
    float* sO  = sH  + TILE * MHP;
    float* sP  = sO  + TILE * 65;
    float* sB1 = sP  + TILE * 4;
    float* sB2 = sB1 + MH;
    float* sG  = sB2 + HD;
    float* sB  = sG  + HD;

    const int tid  = threadIdx.x;
    const int lane = tid & 31;
    const int w    = tid >> 5;
    const int lq   = lane >> 2;
    const int lr   = lane & 3;
    const int mh   = w >> 2;
    const int nq   = w & 3;
    const int mi   = nq >> 1;
    const int ni   = nq & 1;
    const int t128 = tid & 127;
    const int barid = 1 + mh;

    for (int i = tid; i < MH * MH; i += 256) {
        int r = i >> 7, n = i & 127;
        sW1[r * MH + (n ^ ((r & 3) << 3))] = f2tf(nW1[i]);
    }
    for (int i = tid; i < MH * HD; i += 256) {
        int r = i >> 6, n = i & 63;
        sW2[r * HD + (n ^ ((r & 3) << 3))] = f2tf(nW2[i]);
    }
    for (int i = tid; i < MH; i += 256) sB1[i] = nb1[i];
    if (tid < HD) { sB2[tid] = nb2[tid]; sG[tid] = lg[tid]; sB[tid] = lb[tid]; }
    __syncthreads();

    float2 b1p[4], b2p[4];
    #pragma unroll
    for (int j = 0; j < 4; j++) {
        b1p[j] = *(const float2*)&sB1[nq * 32 + 8 * j + 2 * lr];
        b2p[j] = *(const float2*)&sB2[ni * 32 + 8 * j + 2 * lr];
    }

    const int numTiles = (NN + TILE - 1) / TILE;

    float pf[32];
    int t = blockIdx.x;
    if (t < numTiles) {
        const int n0g = t * TILE;
        #pragma unroll
        for (int v = 0; v < 32; v++) {
            int node = min(n0g + mh * 32 + v, NN - 1);
            pf[v] = (t128 < HD) ? h[(size_t)node * HD + t128]
                                : g_agg[(size_t)node * HD + (t128 - HD)];
        }
    }

    for (; t < numTiles; t += gridDim.x) {
        const int n0g = t * TILE;

        #pragma unroll
        for (int v = 0; v < 32; v++)
            sU[(mh * 32 + v) * MHP + t128] = f2tf(pf[v]);

        asm volatile("bar.sync %0, 128;" :: "r"(barid) : "memory");  // (A)

        int tn = t + gridDim.x;
        if (tn < numTiles) {
            const int nn0 = tn * TILE;
            #pragma unroll
            for (int v = 0; v < 32; v++) {
                int node = min(nn0 + mh * 32 + v, NN - 1);
                pf[v] = (t128 < HD) ? h[(size_t)node * HD + t128]
                                    : g_agg[(size_t)node * HD + (t128 - HD)];
            }
        }

        float c1[2][4][4];
        #pragma unroll
        for (int i = 0; i < 2; i++)
            #pragma unroll
            for (int j = 0; j < 4; j++)
                #pragma unroll
                for (int q = 0; q < 4; q++) c1[i][j][q] = 0.f;

        for (int k = 0; k < MH; k += 8) {
            uint32_t a[2][4];
            #pragma unroll
            for (int i = 0; i < 2; i++) {
                int row = mh * 32 + 16 * i + lq;
                a[i][0] = __float_as_uint(sU[row * MHP + k + lr]);
                a[i][1] = __float_as_uint(sU[(row + 8) * MHP + k + lr]);
                a[i][2] = __float_as_uint(sU[row * MHP + k + 4 + lr]);
                a[i][3] = __float_as_uint(sU[(row + 8) * MHP + k + 4 + lr]);
            }
            #pragma unroll
            for (int j = 0; j < 4; j++) {
                int n0 = nq * 32 + 8 * j;
                int cs = (n0 + lq) ^ (lr << 3);
                uint32_t b0 = __float_as_uint(sW1[(k + lr) * MH + cs]);
                uint32_t b1 = __float_as_uint(sW1[(k + 4 + lr) * MH + cs]);
                mma_tf32(c1[0][j], a[0], b0, b1);
                mma_tf32(c1[1][j], a[1], b0, b1);
            }
        }

        #pragma unroll
        for (int i = 0; i < 2; i++) {
            #pragma unroll
            for (int j = 0; j < 4; j++) {
                int row = mh * 32 + 16 * i + lq;
                int col = nq * 32 + 8 * j + 2 * lr;
                uint2 v0, v1;
                v0.x = __float_as_uint(f2tf(fmaxf(c1[i][j][0] + b1p[j].x, 0.f)));
                v0.y = __float_as_uint(f2tf(fmaxf(c1[i][j][1] + b1p[j].y, 0.f)));
                v1.x = __float_as_uint(f2tf(fmaxf(c1[i][j][2] + b1p[j].x, 0.f)));
                v1.y = __float_as_uint(f2tf(fmaxf(c1[i][j][3] + b1p[j].y, 0.f)));
                *(uint2*)&sH[row * MHP + col]       = v0;
                *(uint2*)&sH[(row + 8) * MHP + col] = v1;
            }
        }

        asm volatile("bar.sync %0, 128;" :: "r"(barid) : "memory");  // (B)

        float c2[4][4];
        #pragma unroll
        for (int j = 0; j < 4; j++)
            #pragma unroll
            for (int q = 0; q < 4; q++) c2[j][q] = 0.f;

        const int m0 = mh * 32 + mi * 16;
        for (int k = 0; k < MH; k += 8) {
            uint32_t a[4];
            int row = m0 + lq;
            a[0] = __float_as_uint(sH[row * MHP + k + lr]);
            a[1] = __float_as_uint(sH[(row + 8) * MHP + k + lr]);
            a[2] = __float_as_uint(sH[row * MHP + k + 4 + lr]);
            a[3] = __float_as_uint(sH[(row + 8) * MHP + k + 4 + lr]);
            #pragma unroll
            for (int j = 0; j < 4; j++) {
                int n0 = ni * 32 + 8 * j;
                int cs = (n0 + lq) ^ (lr << 3);
                uint32_t b0 = __float_as_uint(sW2[(k + lr) * HD + cs]);
                uint32_t b1 = __float_as_uint(sW2[(k + 4 + lr) * HD + cs]);
                mma_tf32(c2[j], a, b0, b1);
            }
        }

        {
            int r0 = m0 + lq;
            int r1 = r0 + 8;
            int g0 = min(n0g + r0, NN - 1);
            int g1 = min(n0g + r1, NN - 1);
            float s0 = 0.f, q0 = 0.f, s1 = 0.f, q1 = 0.f;
            #pragma unroll
            for (int j = 0; j < 4; j++) {
                int col = ni * 32 + 8 * j + 2 * lr;
                float2 h0 = *(const float2*)&h[(size_t)g0 * HD + col];
                float2 h1 = *(const float2*)&h[(size_t)g1 * HD + col];
                float x0 = c2[j][0] + b2p[j].x + h0.x;
                float x1 = c2[j][1] + b2p[j].y + h0.y;
                float x2 = c2[j][2] + b2p[j].x + h1.x;
                float x3 = c2[j][3] + b2p[j].y + h1.y;
                sO[r0 * 65 + col]     = x0;
                sO[r0 * 65 + col + 1] = x1;
                sO[r1 * 65 + col]     = x2;
                sO[r1 * 65 + col + 1] = x3;
                s0 += x0 + x1;  q0 = fmaf(x0, x0, fmaf(x1, x1, q0));
                s1 += x2 + x3;  q1 = fmaf(x2, x2, fmaf(x3, x3, q1));
            }
            s0 += __shfl_xor_sync(0xffffffffu, s0, 1);
            s0 += __shfl_xor_sync(0xffffffffu, s0, 2);
            q0 += __shfl_xor_sync(0xffffffffu, q0, 1);
            q0 += __shfl_xor_sync(0xffffffffu, q0, 2);
            s1 += __shfl_xor_sync(0xffffffffu, s1, 1);
            s1 += __shfl_xor_sync(0xffffffffu, s1, 2);
            q1 += __shfl_xor_sync(0xffffffffu, q1, 1);
            q1 += __shfl_xor_sync(0xffffffffu, q1, 2);
            if (lr == 0) {
                sP[r0 * 4 + ni * 2 + 0] = s0;
                sP[r0 * 4 + ni * 2 + 1] = q0;
                sP[r1 * 4 + ni * 2 + 0] = s1;
                sP[r1 * 4 + ni * 2 + 1] = q1;
            }
        }

        asm volatile("bar.sync %0, 128;" :: "r"(barid) : "memory");  // (C)

        {
            int r_l  = mh * 32 + (t128 >> 2);
            int c0   = (t128 & 3) * 16;
            int node = n0g + r_l;
            if (node < NN) {
                float s  = sP[r_l * 4 + 0] + sP[r_l * 4 + 2];
                float q  = sP[r_l * 4 + 1] + sP[r_l * 4 + 3];
                float mu = s * (1.f / HD);
                float vr = fmaxf(q * (1.f / HD) - mu * mu, 0.f);
                float rs = rsqrtf(vr + 1e-5f);
                #pragma unroll
                for (int c = 0; c < 16; c += 2) {
                    float a0 = (sO[r_l * 65 + c0 + c]     - mu) * rs * sG[c0 + c]     + sB[c0 + c];
                    float a1 = (sO[r_l * 65 + c0 + c + 1] - mu) * rs * sG[c0 + c + 1] + sB[c0 + c + 1];
                    *(float2*)&out[(size_t)node * HD + c0 + c] = make_float2(a0, a1);
                }
            }
        }

        asm volatile("bar.sync %0, 128;" :: "r"(barid) : "memory");  // (D)
    }
}

// ---------------------------------------------------------------------------
extern "C" void kernel_launch(void* const* d_in, const int* in_sizes, int n_in,
                              void* d_out, int out_size)
{
    const float* h   = (const float*)d_in[0];
    const int*   ei  = (const int*)d_in[1];     // int32 (JAX default downcast)
    const float* ea  = (const float*)d_in[2];
    const float* eW1 = (const float*)d_in[3];
    const float* eb1 = (const float*)d_in[4];
    const float* eW2 = (const float*)d_in[5];
    const float* eb2 = (const float*)d_in[6];
    const float* nW1 = (const float*)d_in[7];
    const float* nb1 = (const float*)d_in[8];
    const float* nW2 = (const float*)d_in[9];
    const float* nb2 = (const float*)d_in[10];
    const float* lg  = (const float*)d_in[11];
    const float* lb  = (const float*)d_in[12];
    float*       out = (float*)d_out;

    const int smem_prep = (64 * 256 + 128 * 68) * 4;
    const int smem_edge = (8 * MH + MH * HD + ET * MHP) * 4;
    const int smem_node = (MH * MH + MH * HD + 2 * TILE * MHP + TILE * 65
                           + TILE * 4 + MH + 3 * HD) * 4;

    cudaFuncSetAttribute(prep_kernel, cudaFuncAttributeMaxDynamicSharedMemorySize, smem_prep);
    cudaFuncSetAttribute(edge_kernel, cudaFuncAttributeMaxDynamicSharedMemorySize, smem_edge);
    cudaFuncSetAttribute(node_kernel, cudaFuncAttributeMaxDynamicSharedMemorySize, smem_node);

    prep_kernel<<<148, 512, smem_prep>>>(h, eW1, eb1);
    edge_kernel<<<296, 256, smem_edge>>>(ei, ea, eW1, eW2, eb2);
    node_kernel<<<148, 256, smem_node>>>(h, nW1, nb1, nW2, nb2, lg, lb, out);
}

// round 16
// speedup vs baseline: 1.0203x; 1.0143x over previous
#include <cuda_runtime.h>
#include <cstdint>

#define NN    50000
#define NE    800000
#define HD    64
#define MH    128
#define MHP   132    // padded stride (mod 32 == 4 -> conflict-free A-frags)
#define ET    64     // edge tile

// scratch
__device__ float g_agg[(size_t)NN * HD];
__device__ float g_Pcat[(size_t)NN * 256];   // [ h@W_src | h@W_dst + eb1 ]

__device__ __forceinline__ float f2tf(float f) {
    uint32_t u;
    asm("cvt.rna.tf32.f32 %0, %1;" : "=r"(u) : "f"(f));
    return __uint_as_float(u);
}

__device__ __forceinline__ void mma_tf32(float c[4], const uint32_t a[4],
                                         uint32_t b0, uint32_t b1) {
    asm volatile(
        "mma.sync.aligned.m16n8k8.row.col.f32.tf32.tf32.f32 "
        "{%0,%1,%2,%3},{%4,%5,%6,%7},{%8,%9},{%0,%1,%2,%3};"
        : "+f"(c[0]), "+f"(c[1]), "+f"(c[2]), "+f"(c[3])
        : "r"(a[0]), "r"(a[1]), "r"(a[2]), "r"(a[3]), "r"(b0), "r"(b1));
}

// ---------------------------------------------------------------------------
// prep v2: column-split persistent blocks, 2 CTAs/SM.
// Block pair (wsel=0/1) owns Pcat columns [0:128) / [128:256).
//   wsel 0: Pcat[n,0:128]   = h@W_src           (+ zeroes g_agg rows)
//   wsel 1: Pcat[n,128:256] = h@W_dst + eb1
// 256 threads, weights (64x128, 32KB) loaded ONCE per block.
// ---------------------------------------------------------------------------
__global__ __launch_bounds__(256, 2)
void prep_kernel(const float* __restrict__ h, const float* __restrict__ eW1,
                 const float* __restrict__ eb1)
{
    extern __shared__ float sm[];
    float* sW = sm;             // 64 x 128, col-swizzled (this block's W half)
    float* sA = sW + 64 * 128;  // 128 x 68

    const int tid  = threadIdx.x;
    const int lane = tid & 31;
    const int w    = tid >> 5;
    const int lq   = lane >> 2;
    const int lr   = lane & 3;
    const int wsel = blockIdx.x & 1;          // column half
    const int bid2 = blockIdx.x >> 1;         // tile-group id
    const int G2   = gridDim.x >> 1;          // 148

    // weights once per block: rows (wsel? 64..127 : 0..63) of eW1
    for (int i = tid; i < 64 * 128; i += 256) {
        int k = i >> 7, c = i & 127;
        float v = eW1[(wsel * 64 + k) * MH + c];
        sW[k * 128 + (c ^ ((k & 3) << 3))] = f2tf(v);
    }

    const int mh = w >> 1, nc = w & 1;        // 4 (m32) x 2 (n64)
    const int numTiles = (NN + 127) / 128;    // 391

    for (int tile = bid2; tile < numTiles; tile += G2) {
        const int n0g = tile * 128;
        __syncthreads();   // sA free (also covers first-iter weight load)

        if (wsel == 0) {
            for (int i = tid; i < 128 * 16; i += 256) {
                int r = i >> 4, c4 = i & 15;
                int node = n0g + r;
                if (node < NN)
                    reinterpret_cast<float4*>(g_agg)[(size_t)node * 16 + c4] =
                        make_float4(0.f, 0.f, 0.f, 0.f);
            }
        }
        for (int i = tid; i < 128 * 64; i += 256) {
            int r = i >> 6, c = i & 63;
            int node = min(n0g + r, NN - 1);
            sA[r * 68 + c] = f2tf(h[(size_t)node * HD + c]);
        }
        __syncthreads();

        float acc[2][8][4];
        #pragma unroll
        for (int i = 0; i < 2; i++)
            #pragma unroll
            for (int j = 0; j < 8; j++)
                #pragma unroll
                for (int q = 0; q < 4; q++) acc[i][j][q] = 0.f;

        for (int k = 0; k < 64; k += 8) {
            uint32_t a[2][4];
            #pragma unroll
            for (int i = 0; i < 2; i++) {
                int row = mh * 32 + 16 * i + lq;
                a[i][0] = __float_as_uint(sA[row * 68 + k + lr]);
                a[i][1] = __float_as_uint(sA[(row + 8) * 68 + k + lr]);
                a[i][2] = __float_as_uint(sA[row * 68 + k + 4 + lr]);
                a[i][3] = __float_as_uint(sA[(row + 8) * 68 + k + 4 + lr]);
            }
            #pragma unroll
            for (int j = 0; j < 8; j++) {
                int n0 = nc * 64 + 8 * j;
                int cs = (n0 + lq) ^ (lr << 3);
                uint32_t b0 = __float_as_uint(sW[(k + lr) * 128 + cs]);
                uint32_t b1 = __float_as_uint(sW[(k + 4 + lr) * 128 + cs]);
                mma_tf32(acc[0][j], a[0], b0, b1);
                mma_tf32(acc[1][j], a[1], b0, b1);
            }
        }

        #pragma unroll
        for (int i = 0; i < 2; i++) {
            int r0 = mh * 32 + 16 * i + lq;
            int g0 = n0g + r0, g1 = g0 + 8;
            #pragma unroll
            for (int j = 0; j < 8; j++) {
                int cl = nc * 64 + 8 * j + 2 * lr;           // local col 0..127
                float bx = 0.f, by = 0.f;
                if (wsel == 1) {                             // dst half: fold eb1
                    bx = eb1[cl];
                    by = eb1[cl + 1];
                }
                int colg = wsel * MH + cl;
                if (g0 < NN)
                    *(float2*)&g_Pcat[(size_t)g0 * 256 + colg] =
                        make_float2(acc[i][j][0] + bx, acc[i][j][1] + by);
                if (g1 < NN)
                    *(float2*)&g_Pcat[(size_t)g1 * 256 + colg] =
                        make_float2(acc[i][j][2] + bx, acc[i][j][3] + by);
            }
        }
    }
}

// ---------------------------------------------------------------------------
// Edge kernel (exact R13 config): 2 CTAs/SM, reg prefetch, hoisted phase-1
// B-frags, half-block barriers, SMSP-spread phase-2, red.v4 scatter.
// ---------------------------------------------------------------------------
__global__ __launch_bounds__(256, 2)
void edge_kernel(const int* __restrict__ ei,
                 const float* __restrict__ ea,
                 const float* __restrict__ eW1,
                 const float* __restrict__ eW2, const float* __restrict__ eb2)
{
    extern __shared__ float sm[];
    float* sWea = sm;                 // 8 x 128, col-swizzled
    float* sW2  = sWea + 8 * MH;      // 128 x 64, col-swizzled
    float* sH   = sW2 + MH * HD;      // 64 x 132

    const int tid  = threadIdx.x;
    const int lane = tid & 31;
    const int w    = tid >> 5;
    const int lq   = lane >> 2;
    const int lr   = lane & 3;
    const int mh   = w >> 2;
    const int nq   = w & 3;
    const int barid = 1 + mh;
    const bool p2act = (mh == 0) ? (nq < 2) : (nq >= 2);
    const int  nn    = nq & 1;

    for (int i = tid; i < 8 * MH; i += 256) {
        int k = i >> 7, c = i & 127;
        sWea[k * MH + (c ^ ((k & 3) << 3))] = f2tf(eW1[(2 * HD + k) * MH + c]);
    }
    for (int i = tid; i < MH * HD; i += 256) {
        int r = i >> 6, n = i & 63;
        sW2[r * HD + (n ^ ((r & 3) << 3))] = f2tf(eW2[i]);
    }
    __syncthreads();

    uint32_t wb0[4], wb1[4];
    #pragma unroll
    for (int j = 0; j < 4; j++) {
        int n0 = nq * 32 + 8 * j;
        int cs = (n0 + lq) ^ (lr << 3);
        wb0[j] = __float_as_uint(sWea[lr * MH + cs]);
        wb1[j] = __float_as_uint(sWea[(4 + lr) * MH + cs]);
    }

    float2 b2p[4];
    #pragma unroll
    for (int j = 0; j < 4; j++)
        b2p[j] = *(const float2*)&eb2[nn * 32 + 8 * j + 2 * lr];

    int rofs[4];
    #pragma unroll
    for (int q = 0; q < 4; q++)
        rofs[q] = mh * 32 + 16 * (q >> 1) + 8 * (q & 1) + lq;

    const int numTiles = NE / ET;
    const int G = gridDim.x;

    int nS[4], nD[4];
    float nA[8];
    int t = blockIdx.x;
    if (t < numTiles) {
        const int e0 = t * ET;
        #pragma unroll
        for (int q = 0; q < 4; q++) {
            nS[q] = ei[e0 + rofs[q]];
            nD[q] = ei[NE + e0 + rofs[q]];
        }
        #pragma unroll
        for (int i = 0; i < 2; i++) {
            nA[4 * i + 0] = ea[(size_t)(e0 + rofs[2 * i])     * 8 + lr];
            nA[4 * i + 1] = ea[(size_t)(e0 + rofs[2 * i + 1]) * 8 + lr];
            nA[4 * i + 2] = ea[(size_t)(e0 + rofs[2 * i])     * 8 + 4 + lr];
            nA[4 * i + 3] = ea[(size_t)(e0 + rofs[2 * i + 1]) * 8 + 4 + lr];
        }
    }

    for (; t < numTiles; t += G) {
        int cS[4], cD[4];
        uint32_t af[2][4];
        #pragma unroll
        for (int q = 0; q < 4; q++) {
            cS[q] = min(max(nS[q], 0), NN - 1);
            cD[q] = min(max(nD[q], 0), NN - 1);
        }
        #pragma unroll
        for (int i = 0; i < 2; i++)
            #pragma unroll
            for (int q = 0; q < 4; q++)
                af[i][q] = __float_as_uint(f2tf(nA[4 * i + q]));

        int tn = t + G;
        if (tn < numTiles) {
            const int en = tn * ET;
            #pragma unroll
            for (int q = 0; q < 4; q++) {
                nS[q] = ei[en + rofs[q]];
                nD[q] = ei[NE + en + rofs[q]];
            }
            #pragma unroll
            for (int i = 0; i < 2; i++) {
                nA[4 * i + 0] = ea[(size_t)(en + rofs[2 * i])     * 8 + lr];
                nA[4 * i + 1] = ea[(size_t)(en + rofs[2 * i + 1]) * 8 + lr];
                nA[4 * i + 2] = ea[(size_t)(en + rofs[2 * i])     * 8 + 4 + lr];
                nA[4 * i + 3] = ea[(size_t)(en + rofs[2 * i + 1]) * 8 + 4 + lr];
            }
        }

        float c1[2][4][4];
        #pragma unroll
        for (int i = 0; i < 2; i++)
            #pragma unroll
            for (int j = 0; j < 4; j++)
                #pragma unroll
                for (int q = 0; q < 4; q++) c1[i][j][q] = 0.f;

        #pragma unroll
        for (int j = 0; j < 4; j++) {
            mma_tf32(c1[0][j], af[0], wb0[j], wb1[j]);
            mma_tf32(c1[1][j], af[1], wb0[j], wb1[j]);
        }

        // gathered Pcat (bias pre-folded), relu -> sH
        #pragma unroll
        for (int i = 0; i < 2; i++) {
            int r0 = rofs[2 * i];
            int r1 = rofs[2 * i + 1];
            const float* ps0 = g_Pcat + (size_t)cS[2 * i] * 256;
            const float* pd0 = g_Pcat + (size_t)cD[2 * i] * 256 + MH;
            const float* ps1 = g_Pcat + (size_t)cS[2 * i + 1] * 256;
            const float* pd1 = g_Pcat + (size_t)cD[2 * i + 1] * 256 + MH;
            #pragma unroll
            for (int j = 0; j < 4; j++) {
                int col = nq * 32 + 8 * j + 2 * lr;
                float2 s0 = *(const float2*)&ps0[col];
                float2 d0 = *(const float2*)&pd0[col];
                float2 s1 = *(const float2*)&ps1[col];
                float2 d1 = *(const float2*)&pd1[col];
                uint2 v0, v1;
                v0.x = __float_as_uint(f2tf(fmaxf(c1[i][j][0] + s0.x + d0.x, 0.f)));
                v0.y = __float_as_uint(f2tf(fmaxf(c1[i][j][1] + s0.y + d0.y, 0.f)));
                v1.x = __float_as_uint(f2tf(fmaxf(c1[i][j][2] + s1.x + d1.x, 0.f)));
                v1.y = __float_as_uint(f2tf(fmaxf(c1[i][j][3] + s1.y + d1.y, 0.f)));
                *(uint2*)&sH[r0 * MHP + col] = v0;
                *(uint2*)&sH[r1 * MHP + col] = v1;
            }
        }

        asm volatile("bar.sync %0, 128;" :: "r"(barid) : "memory");

        float c2[2][4][4];
        if (p2act) {
            #pragma unroll
            for (int i = 0; i < 2; i++)
                #pragma unroll
                for (int j = 0; j < 4; j++)
                    #pragma unroll
                    for (int q = 0; q < 4; q++) c2[i][j][q] = 0.f;

            for (int k = 0; k < MH; k += 8) {
                uint32_t a[2][4];
                #pragma unroll
                for (int i = 0; i < 2; i++) {
                    int row = rofs[2 * i];
                    a[i][0] = __float_as_uint(sH[row * MHP + k + lr]);
                    a[i][1] = __float_as_uint(sH[(row + 8) * MHP + k + lr]);
                    a[i][2] = __float_as_uint(sH[row * MHP + k + 4 + lr]);
                    a[i][3] = __float_as_uint(sH[(row + 8) * MHP + k + 4 + lr]);
                }
                #pragma unroll
                for (int j = 0; j < 4; j++) {
                    int n0 = nn * 32 + 8 * j;
                    int cs = (n0 + lq) ^ (lr << 3);
                    uint32_t b0 = __float_as_uint(sW2[(k + lr) * HD + cs]);
                    uint32_t b1 = __float_as_uint(sW2[(k + 4 + lr) * HD + cs]);
                    mma_tf32(c2[0][j], a[0], b0, b1);
                    mma_tf32(c2[1][j], a[1], b0, b1);
                }
            }
        }

        asm volatile("bar.sync %0, 128;" :: "r"(barid) : "memory");

        if (p2act) {
            #pragma unroll
            for (int i = 0; i < 2; i++) {
                int d0 = cD[2 * i], d1 = cD[2 * i + 1];
                #pragma unroll
                for (int j = 0; j < 4; j++) {
                    float u0 = c2[i][j][0] + b2p[j].x;
                    float u1 = c2[i][j][1] + b2p[j].y;
                    float u2 = c2[i][j][2] + b2p[j].x;
                    float u3 = c2[i][j][3] + b2p[j].y;
                    float w0 = __shfl_xor_sync(0xffffffffu, u0, 1);
                    float w1 = __shfl_xor_sync(0xffffffffu, u1, 1);
                    float w2 = __shfl_xor_sync(0xffffffffu, u2, 1);
                    float w3 = __shfl_xor_sync(0xffffffffu, u3, 1);
                    if (!(lr & 1)) {
                        int col = nn * 32 + 8 * j + (lr & 2) * 2;
                        float* p0 = g_agg + (size_t)d0 * HD + col;
                        float* p1 = g_agg + (size_t)d1 * HD + col;
                        asm volatile("red.global.add.v4.f32 [%0], {%1, %2, %3, %4};"
                                     :: "l"(p0), "f"(u0), "f"(u1), "f"(w0), "f"(w1)
                                     : "memory");
                        asm volatile("red.global.add.v4.f32 [%0], {%1, %2, %3, %4};"
                                     :: "l"(p1), "f"(u2), "f"(u3), "f"(w2), "f"(w3)
                                     : "memory");
                    }
                }
            }
        }
    }
}

// ---------------------------------------------------------------------------
// Node kernel v2 (R13): half-block decoupled, shuffle-based LayerNorm stats.
// ---------------------------------------------------------------------------
#define TILE 64
__global__ __launch_bounds__(256, 1)
void node_kernel(const float* __restrict__ h,
                 const float* __restrict__ nW1, const float* __restrict__ nb1,
                 const float* __restrict__ nW2, const float* __restrict__ nb2,
                 const float* __restrict__ lg,  const float* __restrict__ lb,
                 float* __restrict__ out)
{
    extern __shared__ float sm[];
    float* sW1 = sm;
    float* sW2 = sW1 + MH * MH;
    float* sU  = sW2 + MH * HD;
    float* sH  = sU  + TILE * MHP;
    float* sO  = sH  + TILE * MHP;
    float* sP  = sO  + TILE * 65;
    float* sB1 = sP  + TILE * 4;
    float* sB2 = sB1 + MH;
    float* sG  = sB2 + HD;
    float* sB  = sG  + HD;

    const int tid  = threadIdx.x;
    const int lane = tid & 31;
    const int w    = tid >> 5;
    const int lq   = lane >> 2;
    const int lr   = lane & 3;
    const int mh   = w >> 2;
    const int nq   = w & 3;
    const int mi   = nq >> 1;
    const int ni   = nq & 1;
    const int t128 = tid & 127;
    const int barid = 1 + mh;

    for (int i = tid; i < MH * MH; i += 256) {
        int r = i >> 7, n = i & 127;
        sW1[r * MH + (n ^ ((r & 3) << 3))] = f2tf(nW1[i]);
    }
    for (int i = tid; i < MH * HD; i += 256) {
        int r = i >> 6, n = i & 63;
        sW2[r * HD + (n ^ ((r & 3) << 3))] = f2tf(nW2[i]);
    }
    for (int i = tid; i < MH; i += 256) sB1[i] = nb1[i];
    if (tid < HD) { sB2[tid] = nb2[tid]; sG[tid] = lg[tid]; sB[tid] = lb[tid]; }
    __syncthreads();

    float2 b1p[4], b2p[4];
    #pragma unroll
    for (int j = 0; j < 4; j++) {
        b1p[j] = *(const float2*)&sB1[nq * 32 + 8 * j + 2 * lr];
        b2p[j] = *(const float2*)&sB2[ni * 32 + 8 * j + 2 * lr];
    }

    const int numTiles = (NN + TILE - 1) / TILE;

    float pf[32];
    int t = blockIdx.x;
    if (t < numTiles) {
        const int n0g = t * TILE;
        #pragma unroll
        for (int v = 0; v < 32; v++) {
            int node = min(n0g + mh * 32 + v, NN - 1);
            pf[v] = (t128 < HD) ? h[(size_t)node * HD + t128]
                                : g_agg[(size_t)node * HD + (t128 - HD)];
        }
    }

    for (; t < numTiles; t += gridDim.x) {
        const int n0g = t * TILE;

        #pragma unroll
        for (int v = 0; v < 32; v++)
            sU[(mh * 32 + v) * MHP + t128] = f2tf(pf[v]);

        asm volatile("bar.sync %0, 128;" :: "r"(barid) : "memory");  // (A)

        int tn = t + gridDim.x;
        if (tn < numTiles) {
            const int nn0 = tn * TILE;
            #pragma unroll
            for (int v = 0; v < 32; v++) {
                int node = min(nn0 + mh * 32 + v, NN - 1);
                pf[v] = (t128 < HD) ? h[(size_t)node * HD + t128]
                                    : g_agg[(size_t)node * HD + (t128 - HD)];
            }
        }

        float c1[2][4][4];
        #pragma unroll
        for (int i = 0; i < 2; i++)
            #pragma unroll
            for (int j = 0; j < 4; j++)
                #pragma unroll
                for (int q = 0; q < 4; q++) c1[i][j][q] = 0.f;

        for (int k = 0; k < MH; k += 8) {
            uint32_t a[2][4];
            #pragma unroll
            for (int i = 0; i < 2; i++) {
                int row = mh * 32 + 16 * i + lq;
                a[i][0] = __float_as_uint(sU[row * MHP + k + lr]);
                a[i][1] = __float_as_uint(sU[(row + 8) * MHP + k + lr]);
                a[i][2] = __float_as_uint(sU[row * MHP + k + 4 + lr]);
                a[i][3] = __float_as_uint(sU[(row + 8) * MHP + k + 4 + lr]);
            }
            #pragma unroll
            for (int j = 0; j < 4; j++) {
                int n0 = nq * 32 + 8 * j;
                int cs = (n0 + lq) ^ (lr << 3);
                uint32_t b0 = __float_as_uint(sW1[(k + lr) * MH + cs]);
                uint32_t b1 = __float_as_uint(sW1[(k + 4 + lr) * MH + cs]);
                mma_tf32(c1[0][j], a[0], b0, b1);
                mma_tf32(c1[1][j], a[1], b0, b1);
            }
        }

        #pragma unroll
        for (int i = 0; i < 2; i++) {
            #pragma unroll
            for (int j = 0; j < 4; j++) {
                int row = mh * 32 + 16 * i + lq;
                int col = nq * 32 + 8 * j + 2 * lr;
                uint2 v0, v1;
                v0.x = __float_as_uint(f2tf(fmaxf(c1[i][j][0] + b1p[j].x, 0.f)));
                v0.y = __float_as_uint(f2tf(fmaxf(c1[i][j][1] + b1p[j].y, 0.f)));
                v1.x = __float_as_uint(f2tf(fmaxf(c1[i][j][2] + b1p[j].x, 0.f)));
                v1.y = __float_as_uint(f2tf(fmaxf(c1[i][j][3] + b1p[j].y, 0.f)));
                *(uint2*)&sH[row * MHP + col]       = v0;
                *(uint2*)&sH[(row + 8) * MHP + col] = v1;
            }
        }

        asm volatile("bar.sync %0, 128;" :: "r"(barid) : "memory");  // (B)

        float c2[4][4];
        #pragma unroll
        for (int j = 0; j < 4; j++)
            #pragma unroll
            for (int q = 0; q < 4; q++) c2[j][q] = 0.f;

        const int m0 = mh * 32 + mi * 16;
        for (int k = 0; k < MH; k += 8) {
            uint32_t a[4];
            int row = m0 + lq;
            a[0] = __float_as_uint(sH[row * MHP + k + lr]);
            a[1] = __float_as_uint(sH[(row + 8) * MHP + k + lr]);
            a[2] = __float_as_uint(sH[row * MHP + k + 4 + lr]);
            a[3] = __float_as_uint(sH[(row + 8) * MHP + k + 4 + lr]);
            #pragma unroll
            for (int j = 0; j < 4; j++) {
                int n0 = ni * 32 + 8 * j;
                int cs = (n0 + lq) ^ (lr << 3);
                uint32_t b0 = __float_as_uint(sW2[(k + lr) * HD + cs]);
                uint32_t b1 = __float_as_uint(sW2[(k + 4 + lr) * HD + cs]);
                mma_tf32(c2[j], a, b0, b1);
            }
        }

        {
            int r0 = m0 + lq;
            int r1 = r0 + 8;
            int g0 = min(n0g + r0, NN - 1);
            int g1 = min(n0g + r1, NN - 1);
            float s0 = 0.f, q0 = 0.f, s1 = 0.f, q1 = 0.f;
            #pragma unroll
            for (int j = 0; j < 4; j++) {
                int col = ni * 32 + 8 * j + 2 * lr;
                float2 h0 = *(const float2*)&h[(size_t)g0 * HD + col];
                float2 h1 = *(const float2*)&h[(size_t)g1 * HD + col];
                float x0 = c2[j][0] + b2p[j].x + h0.x;
                float x1 = c2[j][1] + b2p[j].y + h0.y;
                float x2 = c2[j][2] + b2p[j].x + h1.x;
                float x3 = c2[j][3] + b2p[j].y + h1.y;
                sO[r0 * 65 + col]     = x0;
                sO[r0 * 65 + col + 1] = x1;
                sO[r1 * 65 + col]     = x2;
                sO[r1 * 65 + col + 1] = x3;
                s0 += x0 + x1;  q0 = fmaf(x0, x0, fmaf(x1, x1, q0));
                s1 += x2 + x3;  q1 = fmaf(x2, x2, fmaf(x3, x3, q1));
            }
            s0 += __shfl_xor_sync(0xffffffffu, s0, 1);
            s0 += __shfl_xor_sync(0xffffffffu, s0, 2);
            q0 += __shfl_xor_sync(0xffffffffu, q0, 1);
            q0 += __shfl_xor_sync(0xffffffffu, q0, 2);
            s1 += __shfl_xor_sync(0xffffffffu, s1, 1);
            s1 += __shfl_xor_sync(0xffffffffu, s1, 2);
            q1 += __shfl_xor_sync(0xffffffffu, q1, 1);
            q1 += __shfl_xor_sync(0xffffffffu, q1, 2);
            if (lr == 0) {
                sP[r0 * 4 + ni * 2 + 0] = s0;
                sP[r0 * 4 + ni * 2 + 1] = q0;
                sP[r1 * 4 + ni * 2 + 0] = s1;
                sP[r1 * 4 + ni * 2 + 1] = q1;
            }
        }

        asm volatile("bar.sync %0, 128;" :: "r"(barid) : "memory");  // (C)

        {
            int r_l  = mh * 32 + (t128 >> 2);
            int c0   = (t128 & 3) * 16;
            int node = n0g + r_l;
            if (node < NN) {
                float s  = sP[r_l * 4 + 0] + sP[r_l * 4 + 2];
                float q  = sP[r_l * 4 + 1] + sP[r_l * 4 + 3];
                float mu = s * (1.f / HD);
                float vr = fmaxf(q * (1.f / HD) - mu * mu, 0.f);
                float rs = rsqrtf(vr + 1e-5f);
                #pragma unroll
                for (int c = 0; c < 16; c += 2) {
                    float a0 = (sO[r_l * 65 + c0 + c]     - mu) * rs * sG[c0 + c]     + sB[c0 + c];
                    float a1 = (sO[r_l * 65 + c0 + c + 1] - mu) * rs * sG[c0 + c + 1] + sB[c0 + c + 1];
                    *(float2*)&out[(size_t)node * HD + c0 + c] = make_float2(a0, a1);
                }
            }
        }

        asm volatile("bar.sync %0, 128;" :: "r"(barid) : "memory");  // (D)
    }
}

// ---------------------------------------------------------------------------
extern "C" void kernel_launch(void* const* d_in, const int* in_sizes, int n_in,
                              void* d_out, int out_size)
{
    const float* h   = (const float*)d_in[0];
    const int*   ei  = (const int*)d_in[1];     // int32 (JAX default downcast)
    const float* ea  = (const float*)d_in[2];
    const float* eW1 = (const float*)d_in[3];
    const float* eb1 = (const float*)d_in[4];
    const float* eW2 = (const float*)d_in[5];
    const float* eb2 = (const float*)d_in[6];
    const float* nW1 = (const float*)d_in[7];
    const float* nb1 = (const float*)d_in[8];
    const float* nW2 = (const float*)d_in[9];
    const float* nb2 = (const float*)d_in[10];
    const float* lg  = (const float*)d_in[11];
    const float* lb  = (const float*)d_in[12];
    float*       out = (float*)d_out;

    const int smem_prep = (64 * 128 + 128 * 68) * 4;   // 67,584 B
    const int smem_edge = (8 * MH + MH * HD + ET * MHP) * 4;
    const int smem_node = (MH * MH + MH * HD + 2 * TILE * MHP + TILE * 65
                           + TILE * 4 + MH + 3 * HD) * 4;

    cudaFuncSetAttribute(prep_kernel, cudaFuncAttributeMaxDynamicSharedMemorySize, smem_prep);
    cudaFuncSetAttribute(edge_kernel, cudaFuncAttributeMaxDynamicSharedMemorySize, smem_edge);
    cudaFuncSetAttribute(node_kernel, cudaFuncAttributeMaxDynamicSharedMemorySize, smem_node);

    prep_kernel<<<296, 256, smem_prep>>>(h, eW1, eb1);
    edge_kernel<<<296, 256, smem_edge>>>(ei, ea, eW1, eW2, eb2);
    node_kernel<<<148, 256, smem_node>>>(h, nW1, nb1, nW2, nb2, lg, lb, out);
}